// round 1
// baseline (speedup 1.0000x reference)
#include <cuda_runtime.h>
#include <cstdint>

// ---------------------------------------------------------------------------
// Problem constants
// ---------------------------------------------------------------------------
#define NB 32      // batch
#define IH 225
#define IW 225
#define C  128
#define PH 8       // pooled spatial (ceil(225/32))
#define PW 8
#define OH 7
#define OW 7
#define ITERS 10
#define CG 32      // float4 channel groups (C/4)

// 1 MB scratch for the pooled tensor [NB, PH, PW, C]
__device__ float g_pooled[NB * PH * PW * C];

__device__ __forceinline__ float4 max4(float4 a, float4 b) {
    a.x = fmaxf(a.x, b.x);
    a.y = fmaxf(a.y, b.y);
    a.z = fmaxf(a.z, b.z);
    a.w = fmaxf(a.w, b.w);
    return a;
}

// ---------------------------------------------------------------------------
// Kernel A: segmented 32x32 SAME max-pool. One block per (b, ph, pw) window.
// Warp lanes = 32 float4 channel groups (contiguous 512B per warp access).
// 8 position-groups stripe the window, smem reduce at the end.
// ---------------------------------------------------------------------------
__global__ __launch_bounds__(256) void pool_kernel(const float* __restrict__ x) {
    const int pw = blockIdx.x;
    const int ph = blockIdx.y;
    const int b  = blockIdx.z;
    const int t  = threadIdx.x;
    const int cg = t & 31;    // float4 channel group 0..31
    const int pg = t >> 5;    // position group 0..7

    int h0 = ph * 32 - 15; if (h0 < 0) h0 = 0;
    int h1 = ph * 32 + 16; if (h1 > IH - 1) h1 = IH - 1;
    int w0 = pw * 32 - 15; if (w0 < 0) w0 = 0;
    int w1 = pw * 32 + 16; if (w1 > IW - 1) w1 = IW - 1;
    const int nw = w1 - w0 + 1;

    const float NEG_INF = -__int_as_float(0x7f800000) * 0.0f - 1e30f; // placeholder
    float4 m = make_float4(-1e30f, -1e30f, -1e30f, -1e30f);
    (void)NEG_INF;

    for (int h = h0; h <= h1; ++h) {
        const float4* row =
            reinterpret_cast<const float4*>(x + (((size_t)b * IH + h) * IW + w0) * C) + cg;
        #pragma unroll 4
        for (int w = pg; w < nw; w += 8) {
            float4 v = __ldg(row + (size_t)w * CG);
            m = max4(m, v);
        }
    }

    __shared__ float4 sm[8][CG];
    sm[pg][cg] = m;
    __syncthreads();

    if (pg == 0) {
        #pragma unroll
        for (int g = 1; g < 8; ++g) m = max4(m, sm[g][cg]);
        reinterpret_cast<float4*>(g_pooled)[(((b * PH + ph) * PW + pw) * CG) + cg] = m;
    }
}

// ---------------------------------------------------------------------------
// Kernel B: the 10 precomputed (row,col)-merge iterations + average.
// pooled (1 MB) is L2-resident after kernel A. One thread per output float4.
// ---------------------------------------------------------------------------
struct MergeIdx {
    int ri[ITERS];
    int ci[ITERS];
};

__global__ __launch_bounds__(256) void combine_kernel(float* __restrict__ out, MergeIdx idx) {
    const int total = NB * OH * OW * CG;
    int tid = blockIdx.x * blockDim.x + threadIdx.x;
    if (tid >= total) return;

    const int cg = tid & 31;
    int r = tid >> 5;
    const int ow = r % OW; r /= OW;
    const int oh = r % OH;
    const int b  = r / OH;

    const float4* p = reinterpret_cast<const float4*>(g_pooled);
    float4 acc = make_float4(0.f, 0.f, 0.f, 0.f);

    #pragma unroll
    for (int it = 0; it < ITERS; ++it) {
        const int i = idx.ri[it];
        const int j = idx.ci[it];
        // Row set after merging rows (i, i+1) of the 8-row pooled tensor:
        int r0 = (oh < i) ? oh : ((oh == i) ? i : oh + 1);
        int r1 = (oh == i) ? i + 1 : r0;
        int c0 = (ow < j) ? ow : ((ow == j) ? j : ow + 1);
        int c1 = (ow == j) ? j + 1 : c0;

        float4 m = p[(((b * PH + r0) * PW + c0) * CG) + cg];
        if (c1 != c0) m = max4(m, p[(((b * PH + r0) * PW + c1) * CG) + cg]);
        if (r1 != r0) {
            m = max4(m, p[(((b * PH + r1) * PW + c0) * CG) + cg]);
            if (c1 != c0) m = max4(m, p[(((b * PH + r1) * PW + c1) * CG) + cg]);
        }
        acc.x += m.x; acc.y += m.y; acc.z += m.z; acc.w += m.w;
    }

    const float s = 1.0f / (float)ITERS;
    acc.x *= s; acc.y *= s; acc.z *= s; acc.w *= s;
    reinterpret_cast<float4*>(out)[tid] = acc;
}

// ---------------------------------------------------------------------------
// Host-side MT19937 replicating numpy's legacy RandomState exactly:
//   mt19937_seed (rk_seed) + tempered 32-bit outputs + masked rejection
//   (RandomState.randint for ranges <= 2^32 uses single 32-bit draws, mask=7).
// ---------------------------------------------------------------------------
namespace nprng {
struct MT {
    uint32_t mt[624];
    int idx;
};

static void mt_seed(MT& st, uint32_t s) {
    for (int i = 0; i < 624; ++i) {
        st.mt[i] = s;
        s = 1812433253u * (s ^ (s >> 30)) + (uint32_t)i + 1u;
    }
    st.idx = 624;
}

static uint32_t mt_next(MT& st) {
    if (st.idx >= 624) {
        for (int i = 0; i < 624; ++i) {
            uint32_t y = (st.mt[i] & 0x80000000u) | (st.mt[(i + 1) % 624] & 0x7fffffffu);
            st.mt[i] = st.mt[(i + 397) % 624] ^ (y >> 1) ^ ((y & 1u) ? 0x9908b0dfu : 0u);
        }
        st.idx = 0;
    }
    uint32_t y = st.mt[st.idx++];
    y ^= y >> 11;
    y ^= (y << 7)  & 0x9d2c5680u;
    y ^= (y << 15) & 0xefc60000u;
    y ^= y >> 18;
    return y;
}

// randint(0, 7): rng = 6, mask = 7, masked rejection on 32-bit draws
static int randint7(MT& st) {
    for (;;) {
        uint32_t v = mt_next(st) & 7u;
        if (v <= 6u) return (int)v;
    }
}
}  // namespace nprng

extern "C" void kernel_launch(void* const* d_in, const int* in_sizes, int n_in,
                              void* d_out, int out_size) {
    (void)in_sizes; (void)n_in; (void)out_size;
    const float* x = (const float*)d_in[0];
    float* out = (float*)d_out;

    // Deterministic host-side index computation (capture-time only, no device work)
    MergeIdx idx;
    for (int it = 0; it < ITERS; ++it) {
        nprng::MT st;
        nprng::mt_seed(st, 42u + (uint32_t)it);
        idx.ri[it] = nprng::randint7(st);
        idx.ci[it] = nprng::randint7(st);
    }

    dim3 gridA(PW, PH, NB);
    pool_kernel<<<gridA, 256>>>(x);

    const int totalB = NB * OH * OW * CG;
    combine_kernel<<<(totalB + 255) / 256, 256>>>(out, idx);
}

// round 2
// speedup vs baseline: 1.0464x; 1.0464x over previous
#include <cuda_runtime.h>
#include <cstdint>

// ---------------------------------------------------------------------------
// Problem constants
// ---------------------------------------------------------------------------
#define NB 32      // batch
#define IH 225
#define IW 225
#define C  128
#define PH 8       // pooled spatial (ceil(225/32))
#define PW 8
#define OH 7
#define OW 7
#define ITERS 10
#define CG 32      // float4 channel groups (C/4)

// 1 MB scratch for the pooled tensor [NB, PH, PW, C]
__device__ float g_pooled[NB * PH * PW * C];

__device__ __forceinline__ float4 max4(float4 a, float4 b) {
    a.x = fmaxf(a.x, b.x);
    a.y = fmaxf(a.y, b.y);
    a.z = fmaxf(a.z, b.z);
    a.w = fmaxf(a.w, b.w);
    return a;
}

// ---------------------------------------------------------------------------
// Kernel A: segmented 32x32 SAME max-pool. One block per (b, ph, pw) window.
// Warp lanes = 32 float4 channel groups (contiguous 512B per warp access).
// 8 position-groups stripe the window; h-loop unrolled x2 with independent
// accumulators for 8 concurrent LDG.128 per thread. smem reduce at the end.
// ---------------------------------------------------------------------------
__global__ __launch_bounds__(256) void pool_kernel(const float* __restrict__ x) {
    const int pw = blockIdx.x;
    const int ph = blockIdx.y;
    const int b  = blockIdx.z;
    const int t  = threadIdx.x;
    const int cg = t & 31;    // float4 channel group 0..31
    const int pg = t >> 5;    // position group 0..7

    int h0 = ph * 32 - 15; if (h0 < 0) h0 = 0;
    int h1 = ph * 32 + 16; if (h1 > IH - 1) h1 = IH - 1;
    int w0 = pw * 32 - 15; if (w0 < 0) w0 = 0;
    int w1 = pw * 32 + 16; if (w1 > IW - 1) w1 = IW - 1;
    const int nw = w1 - w0 + 1;

    const size_t rowstride = (size_t)IW * CG;  // in float4 units
    const float4* base =
        reinterpret_cast<const float4*>(x) +
        (size_t)b * IH * rowstride + (size_t)w0 * CG + cg;

    float4 m0 = make_float4(-1e30f, -1e30f, -1e30f, -1e30f);
    float4 m1 = m0;

    int h = h0;
    for (; h + 1 <= h1; h += 2) {
        const float4* r0 = base + (size_t)h * rowstride;
        const float4* r1 = r0 + rowstride;
        #pragma unroll
        for (int k = 0; k < 4; ++k) {
            const int w = pg + 8 * k;
            if (w < nw) {
                m0 = max4(m0, __ldg(r0 + (size_t)w * CG));
                m1 = max4(m1, __ldg(r1 + (size_t)w * CG));
            }
        }
    }
    if (h <= h1) {
        const float4* r0 = base + (size_t)h * rowstride;
        #pragma unroll
        for (int k = 0; k < 4; ++k) {
            const int w = pg + 8 * k;
            if (w < nw) m0 = max4(m0, __ldg(r0 + (size_t)w * CG));
        }
    }
    m0 = max4(m0, m1);

    __shared__ float4 sm[8][CG];
    sm[pg][cg] = m0;
    __syncthreads();

    if (pg == 0) {
        #pragma unroll
        for (int g = 1; g < 8; ++g) m0 = max4(m0, sm[g][cg]);
        reinterpret_cast<float4*>(g_pooled)[(((b * PH + ph) * PW + pw) * CG) + cg] = m0;
    }
}

// ---------------------------------------------------------------------------
// Kernel B: the 10 precomputed (row,col)-merge iterations + average.
// One thread per output FLOAT (not float4): 784 blocks -> ~5.3 blocks/SM,
// enough occupancy to hide L2 latency. All reads hit L2 (1 MB pooled tensor).
// ---------------------------------------------------------------------------
struct MergeIdx {
    int ri[ITERS];
    int ci[ITERS];
};

__global__ __launch_bounds__(256) void combine_kernel(float* __restrict__ out, MergeIdx idx) {
    const int total = NB * OH * OW * C;
    int tid = blockIdx.x * blockDim.x + threadIdx.x;
    if (tid >= total) return;

    const int c = tid & (C - 1);
    int r = tid >> 7;
    const int ow = r % OW; r /= OW;
    const int oh = r % OH;
    const int b  = r / OH;

    const float* p = g_pooled;
    const int bbase = b * PH * PW * C + c;
    float acc = 0.f;

    #pragma unroll
    for (int it = 0; it < ITERS; ++it) {
        const int i = idx.ri[it];
        const int j = idx.ci[it];
        // Row set after merging rows (i, i+1) of the 8-row pooled tensor:
        int r0 = (oh < i) ? oh : ((oh == i) ? i : oh + 1);
        int r1 = (oh == i) ? i + 1 : r0;
        int c0 = (ow < j) ? ow : ((ow == j) ? j : ow + 1);
        int c1 = (ow == j) ? j + 1 : c0;

        float m = __ldg(p + bbase + (r0 * PW + c0) * C);
        if (c1 != c0) m = fmaxf(m, __ldg(p + bbase + (r0 * PW + c1) * C));
        if (r1 != r0) {
            m = fmaxf(m, __ldg(p + bbase + (r1 * PW + c0) * C));
            if (c1 != c0) m = fmaxf(m, __ldg(p + bbase + (r1 * PW + c1) * C));
        }
        acc += m;
    }

    out[tid] = acc * (1.0f / (float)ITERS);
}

// ---------------------------------------------------------------------------
// Host-side MT19937 replicating numpy's legacy RandomState exactly:
//   mt19937_seed (rk_seed) + tempered 32-bit outputs + masked rejection
//   (RandomState.randint for ranges <= 2^32 uses single 32-bit draws, mask=7).
// ---------------------------------------------------------------------------
namespace nprng {
struct MT {
    uint32_t mt[624];
    int idx;
};

static void mt_seed(MT& st, uint32_t s) {
    for (int i = 0; i < 624; ++i) {
        st.mt[i] = s;
        s = 1812433253u * (s ^ (s >> 30)) + (uint32_t)i + 1u;
    }
    st.idx = 624;
}

static uint32_t mt_next(MT& st) {
    if (st.idx >= 624) {
        for (int i = 0; i < 624; ++i) {
            uint32_t y = (st.mt[i] & 0x80000000u) | (st.mt[(i + 1) % 624] & 0x7fffffffu);
            st.mt[i] = st.mt[(i + 397) % 624] ^ (y >> 1) ^ ((y & 1u) ? 0x9908b0dfu : 0u);
        }
        st.idx = 0;
    }
    uint32_t y = st.mt[st.idx++];
    y ^= y >> 11;
    y ^= (y << 7)  & 0x9d2c5680u;
    y ^= (y << 15) & 0xefc60000u;
    y ^= y >> 18;
    return y;
}

// randint(0, 7): rng = 6, mask = 7, masked rejection on 32-bit draws
static int randint7(MT& st) {
    for (;;) {
        uint32_t v = mt_next(st) & 7u;
        if (v <= 6u) return (int)v;
    }
}
}  // namespace nprng

extern "C" void kernel_launch(void* const* d_in, const int* in_sizes, int n_in,
                              void* d_out, int out_size) {
    (void)in_sizes; (void)n_in; (void)out_size;
    const float* x = (const float*)d_in[0];
    float* out = (float*)d_out;

    // Deterministic host-side index computation (capture-time only, no device work)
    MergeIdx idx;
    for (int it = 0; it < ITERS; ++it) {
        nprng::MT st;
        nprng::mt_seed(st, 42u + (uint32_t)it);
        idx.ri[it] = nprng::randint7(st);
        idx.ci[it] = nprng::randint7(st);
    }

    dim3 gridA(PW, PH, NB);
    pool_kernel<<<gridA, 256>>>(x);

    const int totalB = NB * OH * OW * C;
    combine_kernel<<<(totalB + 255) / 256, 256>>>(out, idx);
}

// round 4
// speedup vs baseline: 1.0656x; 1.0183x over previous
#include <cuda_runtime.h>
#include <cstdint>
#include <cstring>

// ---------------------------------------------------------------------------
// Problem constants
// ---------------------------------------------------------------------------
#define NB 32      // batch
#define IH 225
#define IW 225
#define C  128
#define PH 8       // pooled spatial (ceil(225/32))
#define PW 8
#define OH 7
#define OW 7
#define ITERS 10
#define CG 32      // float4 channel groups (C/4)
#define NS (OH * OW)   // 49 output spatial positions

// 1 MB scratch for the pooled tensor [NB, PH, PW, C]
__device__ float g_pooled[NB * PH * PW * C];

__device__ __forceinline__ float4 max4(float4 a, float4 b) {
    a.x = fmaxf(a.x, b.x);
    a.y = fmaxf(a.y, b.y);
    a.z = fmaxf(a.z, b.z);
    a.w = fmaxf(a.w, b.w);
    return a;
}

// ---------------------------------------------------------------------------
// Kernel A: segmented 32x32 SAME max-pool. One block per (b, ph, pw) window.
// Warp lanes = 32 float4 channel groups (contiguous 512B per warp access).
// Interior windows (nw==32) take an unpredicated fully-unrolled path.
// ---------------------------------------------------------------------------
__global__ __launch_bounds__(256) void pool_kernel(const float* __restrict__ x) {
    const int pw = blockIdx.x;
    const int ph = blockIdx.y;
    const int b  = blockIdx.z;
    const int t  = threadIdx.x;
    const int cg = t & 31;    // float4 channel group 0..31
    const int pg = t >> 5;    // position group 0..7

    int h0 = ph * 32 - 15; if (h0 < 0) h0 = 0;
    int h1 = ph * 32 + 16; if (h1 > IH - 1) h1 = IH - 1;
    int w0 = pw * 32 - 15; if (w0 < 0) w0 = 0;
    int w1 = pw * 32 + 16; if (w1 > IW - 1) w1 = IW - 1;
    const int nw = w1 - w0 + 1;

    const size_t rowstride = (size_t)IW * CG;  // in float4 units
    const float4* base =
        reinterpret_cast<const float4*>(x) +
        (size_t)b * IH * rowstride + (size_t)w0 * CG + cg;

    float4 m0 = make_float4(-1e30f, -1e30f, -1e30f, -1e30f);
    float4 m1 = m0;

    if (nw == 32) {
        // Interior: 4 positions per thread, no predicates.
        int h = h0;
        for (; h + 1 <= h1; h += 2) {
            const float4* r0 = base + (size_t)h * rowstride;
            const float4* r1 = r0 + rowstride;
            #pragma unroll
            for (int k = 0; k < 4; ++k) {
                const size_t off = (size_t)(pg + 8 * k) * CG;
                m0 = max4(m0, __ldg(r0 + off));
                m1 = max4(m1, __ldg(r1 + off));
            }
        }
        if (h <= h1) {
            const float4* r0 = base + (size_t)h * rowstride;
            #pragma unroll
            for (int k = 0; k < 4; ++k)
                m0 = max4(m0, __ldg(r0 + (size_t)(pg + 8 * k) * CG));
        }
    } else {
        int h = h0;
        for (; h + 1 <= h1; h += 2) {
            const float4* r0 = base + (size_t)h * rowstride;
            const float4* r1 = r0 + rowstride;
            #pragma unroll
            for (int k = 0; k < 5; ++k) {
                const int w = pg + 8 * k;
                if (w < nw) {
                    m0 = max4(m0, __ldg(r0 + (size_t)w * CG));
                    m1 = max4(m1, __ldg(r1 + (size_t)w * CG));
                }
            }
        }
        if (h <= h1) {
            const float4* r0 = base + (size_t)h * rowstride;
            #pragma unroll
            for (int k = 0; k < 5; ++k) {
                const int w = pg + 8 * k;
                if (w < nw) m0 = max4(m0, __ldg(r0 + (size_t)w * CG));
            }
        }
    }
    m0 = max4(m0, m1);

    __shared__ float4 sm[8][CG];
    sm[pg][cg] = m0;
    __syncthreads();

    if (pg == 0) {
        #pragma unroll
        for (int g = 1; g < 8; ++g) m0 = max4(m0, sm[g][cg]);
        reinterpret_cast<float4*>(g_pooled)[(((b * PH + ph) * PW + pw) * CG) + cg] = m0;
    }
}

// ---------------------------------------------------------------------------
// Kernel B: weighted-max combine with a fully host-precomputed table.
// Per output position s: n entries, each (packed 4 cell ids, shape, count).
// Warp per (b, s); lane = float4 channel group. Zero index math on device.
// ---------------------------------------------------------------------------
struct CombTab {
    uint32_t      cells[NS][ITERS];   // 4 packed cell ids (r*8+c), dup-padded
    unsigned char shape[NS][ITERS];   // 0 = 1 cell, 1 = 2 cells, 2 = 4 cells
    unsigned char cnt[NS][ITERS];     // multiplicity across iterations
    unsigned char n[NS];              // entries for this position
};

__global__ __launch_bounds__(128) void combine_kernel(float* __restrict__ out, CombTab tab) {
    const int gw = blockIdx.x * 4 + (threadIdx.x >> 5);   // warp = (b, s)
    if (gw >= NB * NS) return;
    const int cg = threadIdx.x & 31;
    const int b  = gw / NS;
    const int s  = gw - b * NS;

    const float4* p = reinterpret_cast<const float4*>(g_pooled) + (size_t)b * PH * PW * CG + cg;
    const int n = tab.n[s];

    float4 acc = make_float4(0.f, 0.f, 0.f, 0.f);
    for (int e = 0; e < n; ++e) {
        const uint32_t pk = tab.cells[s][e];
        const int sh = tab.shape[s][e];
        const float w = (float)tab.cnt[s][e] * (1.0f / (float)ITERS);

        float4 m = __ldg(p + (size_t)(pk & 63u) * CG);
        if (sh >= 1) m = max4(m, __ldg(p + (size_t)((pk >> 8) & 63u) * CG));
        if (sh == 2) {
            m = max4(m, __ldg(p + (size_t)((pk >> 16) & 63u) * CG));
            m = max4(m, __ldg(p + (size_t)((pk >> 24) & 63u) * CG));
        }
        acc.x += m.x * w; acc.y += m.y * w; acc.z += m.z * w; acc.w += m.w * w;
    }
    reinterpret_cast<float4*>(out)[(size_t)gw * CG + cg] = acc;
}

// ---------------------------------------------------------------------------
// Host-side MT19937 replicating numpy's legacy RandomState exactly.
// ---------------------------------------------------------------------------
namespace nprng {
struct MT { uint32_t mt[624]; int idx; };

static void mt_seed(MT& st, uint32_t s) {
    for (int i = 0; i < 624; ++i) {
        st.mt[i] = s;
        s = 1812433253u * (s ^ (s >> 30)) + (uint32_t)i + 1u;
    }
    st.idx = 624;
}

static uint32_t mt_next(MT& st) {
    if (st.idx >= 624) {
        for (int i = 0; i < 624; ++i) {
            uint32_t y = (st.mt[i] & 0x80000000u) | (st.mt[(i + 1) % 624] & 0x7fffffffu);
            st.mt[i] = st.mt[(i + 397) % 624] ^ (y >> 1) ^ ((y & 1u) ? 0x9908b0dfu : 0u);
        }
        st.idx = 0;
    }
    uint32_t y = st.mt[st.idx++];
    y ^= y >> 11;
    y ^= (y << 7)  & 0x9d2c5680u;
    y ^= (y << 15) & 0xefc60000u;
    y ^= y >> 18;
    return y;
}

// randint(0, 7): masked rejection, mask = 7
static int randint7(MT& st) {
    for (;;) {
        uint32_t v = mt_next(st) & 7u;
        if (v <= 6u) return (int)v;
    }
}
}  // namespace nprng

extern "C" void kernel_launch(void* const* d_in, const int* in_sizes, int n_in,
                              void* d_out, int out_size) {
    (void)in_sizes; (void)n_in; (void)out_size;
    const float* x = (const float*)d_in[0];
    float* out = (float*)d_out;

    // ---- Deterministic host-side table construction (capture-time only) ----
    int ri[ITERS], ci[ITERS];
    for (int it = 0; it < ITERS; ++it) {
        nprng::MT st;
        nprng::mt_seed(st, 42u + (uint32_t)it);
        ri[it] = nprng::randint7(st);
        ci[it] = nprng::randint7(st);
    }

    CombTab tab;
    memset(&tab, 0, sizeof(tab));
    for (int s = 0; s < NS; ++s) {
        const int oh = s / OW;
        const int ow = s - oh * OW;
        int nE = 0;
        for (int it = 0; it < ITERS; ++it) {
            const int i = ri[it], j = ci[it];
            int r0 = (oh < i) ? oh : ((oh == i) ? i : oh + 1);
            int r1 = (oh == i) ? i + 1 : r0;
            int c0 = (ow < j) ? ow : ((ow == j) ? j : ow + 1);
            int c1 = (ow == j) ? j + 1 : c0;

            // Build unique cell list (canonical order).
            unsigned char cl[4];
            int ncell = 0;
            cl[ncell++] = (unsigned char)(r0 * PW + c0);
            if (c1 != c0) cl[ncell++] = (unsigned char)(r0 * PW + c1);
            if (r1 != r0) {
                cl[ncell++] = (unsigned char)(r1 * PW + c0);
                if (c1 != c0) cl[ncell++] = (unsigned char)(r1 * PW + c1);
            }
            // Pad by repeating last cell.
            for (int k = ncell; k < 4; ++k) cl[k] = cl[ncell - 1];
            uint32_t packed = (uint32_t)cl[0] | ((uint32_t)cl[1] << 8) |
                              ((uint32_t)cl[2] << 16) | ((uint32_t)cl[3] << 24);
            unsigned char shape = (ncell == 1) ? 0 : ((ncell == 2) ? 1 : 2);

            // Dedupe across iterations.
            int found = -1;
            for (int e = 0; e < nE; ++e)
                if (tab.cells[s][e] == packed && tab.shape[s][e] == shape) { found = e; break; }
            if (found >= 0) {
                tab.cnt[s][found]++;
            } else {
                tab.cells[s][nE] = packed;
                tab.shape[s][nE] = shape;
                tab.cnt[s][nE] = 1;
                nE++;
            }
        }
        tab.n[s] = (unsigned char)nE;
    }

    dim3 gridA(PW, PH, NB);
    pool_kernel<<<gridA, 256>>>(x);

    const int nwarps = NB * NS;                 // 1568 warps
    combine_kernel<<<(nwarps + 3) / 4, 128>>>(out, tab);
}